// round 15
// baseline (speedup 1.0000x reference)
#include <cuda_runtime.h>
#include <cstdint>

#define NN 20000
#define DD 32
#define TM 48            // nodes per LSTM block
#define HP 68            // hs row stride (floats), multiple of 4 for LDS.128
#define GP 49            // gates row stride: >= TM columns, odd -> conflict-free

typedef unsigned long long ull;

// ---------------- scratch (static device globals; no allocation) ----------------
__device__ float g_Z[NN * 256];     // UNIT-MAJOR: col = 4*unit + gate (i,f,g,o)
__device__ float g_hA[NN * 64];
__device__ float g_hB[NN * 64];
__device__ float g_agg[NN * 64];
__device__ int   g_snbr[NN * DD];

// ---------------- helpers ----------------
__device__ __forceinline__ ull pack2(float lo, float hi) {
    ull d; asm("mov.b64 %0, {%1,%2};" : "=l"(d) : "f"(lo), "f"(hi)); return d;
}
__device__ __forceinline__ void unpack2(ull v, float& lo, float& hi) {
    asm("mov.b64 {%0,%1}, %2;" : "=f"(lo), "=f"(hi) : "l"(v));
}
__device__ __forceinline__ ull fma2(ull a, ull b, ull c) {
    ull d; asm("fma.rn.f32x2 %0, %1, %2, %3;" : "=l"(d) : "l"(a), "l"(b), "l"(c)); return d;
}
__device__ __forceinline__ float tanhf_a(float x) {
    float r; asm("tanh.approx.f32 %0, %1;" : "=f"(r) : "f"(x)); return r;
}
__device__ __forceinline__ float sigf(float x) {        // 1 MUFU + 1 FMA
    return fmaf(tanhf_a(0.5f * x), 0.5f, 0.5f);
}
__device__ __forceinline__ const float* sel_h(const float* ext, int s) {
    return s == 0 ? g_hA : (s == 1 ? g_hB : ext);
}

// ---------------- 0) dummy launch: keeps lstm layer-0 at ncu -s 5 ----------------
__global__ void dummy_kernel() {}

// ---------------- 1) per-row bitonic sort of 32 neighbor ids (warp per node) ----------------
__global__ void sort_kernel(const int* __restrict__ nbr) {
    int lane = threadIdx.x & 31;
    int node = (blockIdx.x * blockDim.x + threadIdx.x) >> 5;
    if (node >= NN) return;
    int v = nbr[node * DD + lane];
#pragma unroll
    for (int k = 2; k <= 32; k <<= 1) {
        for (int j = k >> 1; j > 0; j >>= 1) {
            int o = __shfl_xor_sync(0xffffffffu, v, j);
            bool up = ((lane & k) == 0);
            bool lower = ((lane & j) == 0);
            int mn = min(v, o), mx = max(v, o);
            v = (up == lower) ? mn : mx;
        }
    }
    g_snbr[node * DD + lane] = v;
}

// ---------------- 2) Z = h @ W_ih^T + biases, UNIT-MAJOR col order (col = 4u+g) ----------------
#define ZNB 16
__global__ void z_kernel(const float* __restrict__ hext, int hselv,
                         const float* __restrict__ Wih,
                         const float* __restrict__ bih,
                         const float* __restrict__ bhh, int in_d) {
    extern __shared__ float sm[];
    float* Ws = sm;                 // [in_d][256] transposed, reordered cols
    float* hs = sm + in_d * 256;    // [ZNB][in_d]
    const float* hin = sel_h(hext, hselv);
    int tid = threadIdx.x;
    int base = blockIdx.x * ZNB;

    for (int idx = tid; idx < in_d * 256; idx += 256) {
        int col = idx & 255, k = idx >> 8;
        int wrow = (col & 3) * 64 + (col >> 2);     // gate*64 + unit
        Ws[idx] = Wih[wrow * in_d + k];
    }
    for (int idx = tid; idx < ZNB * in_d; idx += 256) {
        int n = idx / in_d, k = idx - n * in_d;
        int gn = base + n;
        hs[idx] = (gn < NN) ? hin[gn * in_d + k] : 0.0f;
    }
    __syncthreads();

    int col = tid;
    int wrow = (col & 3) * 64 + (col >> 2);
    float bias = bih[wrow] + bhh[wrow];
    float acc[ZNB];
#pragma unroll
    for (int n = 0; n < ZNB; n++) acc[n] = bias;
    for (int k = 0; k < in_d; k++) {
        float w = Ws[k * 256 + col];
#pragma unroll
        for (int n = 0; n < ZNB; n++) acc[n] += hs[n * in_d + k] * w;
    }
#pragma unroll
    for (int n = 0; n < ZNB; n++) {
        int gn = base + n;
        if (gn < NN) g_Z[gn * 256 + col] = acc[n];
    }
}

// ---------------- 3) recurrent LSTM: WEIGHT-STATIONARY fp32 GEMM ----------------
// 8 warps. GEMM role: warp w -> gate g=w&3, unit-half uh=w>>2; thread unit u=uh*32+lane,
// gate-row j=g*64+u held in 32 f32x2 regs (k-pairs). h broadcast from hs[n][HP] via LDS.128.
// Cell role: warp w -> unit-half uh=w>>2, node-quarter (w&3)*12; c-state in regs.
__global__ __launch_bounds__(256, 2)
void lstm_ws_kernel(const float* __restrict__ Whh) {
    extern __shared__ float smf[];
    float* hs = smf;                       // [TM][HP]  h_{t-1}/h_t (single buffer, 2 barriers)
    float* gs = hs + TM * HP;              // [256][GP] gate partial sums (Whh part)
    int* sn = (int*)(gs + 256 * GP);       // [TM][DD]  Z row offsets (r*256)

    int tid = threadIdx.x;
    int lane = tid & 31, w = tid >> 5;
    int g = w & 3, uh = w >> 2;
    int u = uh * 32 + lane;                // unit for BOTH roles
    int j = g * 64 + u;                    // GEMM gate-row
    int base = blockIdx.x * TM;

    // weights -> registers (one-time, float4 row reads, L2-cached)
    ull wk[32];
    {
        const float4* wrow = (const float4*)(Whh + j * 64);
#pragma unroll
        for (int m4 = 0; m4 < 16; m4++) {
            float4 v = __ldg(&wrow[m4]);
            wk[2 * m4]     = pack2(v.x, v.y);
            wk[2 * m4 + 1] = pack2(v.z, v.w);
        }
    }

    for (int idx = tid; idx < TM * DD; idx += 256) {
        int n = idx >> 5, d = idx & 31;
        int gn = base + n;
        sn[idx] = ((gn < NN) ? g_snbr[gn * DD + d] : 0) << 8;
    }
    __syncthreads();

    const int ns = (w & 3) * 12;           // cell node range [ns, ns+12)
    float c[12];
#pragma unroll
    for (int i = 0; i < 12; i++) c[i] = 0.0f;

#pragma unroll 1
    for (int t = 0; t < DD; t++) {
        if (t > 0) {
            // gates_Whh[j][n] = sum_k h[n][k] * W[j][k], k-pairs packed in f32x2
#pragma unroll 1
            for (int pass = 0; pass < TM / 8; pass++) {
                const float* hbase = hs + pass * 8 * HP;
                ull acc[8];
#pragma unroll
                for (int n8 = 0; n8 < 8; n8++) acc[n8] = 0ull;
#pragma unroll
                for (int m4 = 0; m4 < 16; m4++) {
#pragma unroll
                    for (int n8 = 0; n8 < 8; n8++) {
                        ulonglong2 hv = *(const ulonglong2*)(hbase + n8 * HP + 4 * m4);
                        acc[n8] = fma2(hv.x, wk[2 * m4], acc[n8]);
                        acc[n8] = fma2(hv.y, wk[2 * m4 + 1], acc[n8]);
                    }
                }
#pragma unroll
                for (int n8 = 0; n8 < 8; n8++) {
                    float lo, hi;
                    unpack2(acc[n8], lo, hi);
                    gs[j * GP + pass * 8 + n8] = lo + hi;   // lane stride GP=49: conflict-free
                }
            }
            __syncthreads();   // gates visible to cell phase
        }

        // cell phase: 12 (node, unit) pairs per thread
#pragma unroll 4
        for (int i = 0; i < 12; i++) {
            int n = ns + i;
            const float* zr = g_Z + sn[n * DD + t];
            float4 z = *(const float4*)(zr + 4 * u);        // (i,f,g,o) for unit u, coalesced
            float di = 0.0f, df = 0.0f, dg = 0.0f, dq = 0.0f;
            if (t > 0) {
                di = gs[(0 * 64 + u) * GP + n];             // lane stride 49: conflict-free
                df = gs[(1 * 64 + u) * GP + n];
                dg = gs[(2 * 64 + u) * GP + n];
                dq = gs[(3 * 64 + u) * GP + n];
            }
            float ig = sigf(z.x + di);
            float fg = sigf(z.y + df);
            float gg = tanhf_a(z.z + dg);
            float og = sigf(z.w + dq);
            float cc = fg * c[i] + ig * gg;
            c[i] = cc;
            float hh = og * tanhf_a(cc);
            if (t == DD - 1) {
                int gn = base + n;
                if (gn < NN) g_agg[(size_t)gn * 64 + u] = hh;
            } else {
                hs[n * HP + u] = hh;                        // lanes consecutive: conflict-free
            }
        }
        __syncthreads();   // h_t complete before next GEMM reads
    }
}

// ---------------- 4) h_out = relu([h_in, agg] @ Wl^T + bl) ----------------
#define CNB 32
__global__ void combine_kernel(const float* __restrict__ hext, int hselv,
                               const float* __restrict__ Wl,
                               const float* __restrict__ bl,
                               int oselv, int in_d) {
    int K = in_d + 64;
    extern __shared__ float sm[];
    float* Wls = sm;               // [K][64] transposed
    float* cats = sm + K * 64;     // [CNB][K]
    const float* hin = sel_h(hext, hselv);
    float* hout = (oselv == 0) ? g_hA : g_hB;

    int tid = threadIdx.x;
    int j = tid & 63;
    int grp = tid >> 6;
    int base = blockIdx.x * CNB;

    for (int idx = tid; idx < K * 64; idx += 256) {
        int k = idx >> 6, j2 = idx & 63;
        Wls[idx] = Wl[j2 * K + k];
    }
    for (int idx = tid; idx < CNB * K; idx += 256) {
        int n = idx / K, k = idx - n * K;
        int gn = base + n;
        float v = 0.0f;
        if (gn < NN) v = (k < in_d) ? hin[gn * in_d + k] : g_agg[gn * 64 + (k - in_d)];
        cats[idx] = v;
    }
    __syncthreads();

    float acc[8];
#pragma unroll
    for (int i = 0; i < 8; i++) acc[i] = 0.0f;
    for (int k = 0; k < K; k++) {
        float w = Wls[k * 64 + j];
#pragma unroll
        for (int i = 0; i < 8; i++) acc[i] += cats[(grp * 8 + i) * K + k] * w;
    }
    float bj = bl[j];
#pragma unroll
    for (int i = 0; i < 8; i++) {
        int gn = base + grp * 8 + i;
        if (gn < NN) hout[gn * 64 + j] = fmaxf(acc[i] + bj, 0.0f);
    }
}

// ---------------- 5) out = h @ W_out^T + b_out  (warp per node) ----------------
__global__ void out_kernel(int hselv, const float* __restrict__ Wout,
                           const float* __restrict__ bout, float* __restrict__ out) {
    const float* hin = sel_h(nullptr, hselv);
    int lane = threadIdx.x & 31;
    int node = (blockIdx.x * blockDim.x + threadIdx.x) >> 5;
    if (node >= NN) return;
    float s = hin[node * 64 + lane] * Wout[lane] + hin[node * 64 + 32 + lane] * Wout[32 + lane];
#pragma unroll
    for (int d = 16; d > 0; d >>= 1) s += __shfl_xor_sync(0xffffffffu, s, d);
    if (lane == 0) out[node] = s + bout[0];
}

// ---------------- launcher ----------------
extern "C" void kernel_launch(void* const* d_in, const int* in_sizes, int n_in,
                              void* d_out, int out_size) {
    const float* nf = (const float*)d_in[0];
    const int* nbr = (const int*)d_in[1];
    const float* Wih[3] = {(const float*)d_in[2], (const float*)d_in[8], (const float*)d_in[14]};
    const float* Whh[3] = {(const float*)d_in[3], (const float*)d_in[9], (const float*)d_in[15]};
    const float* bih[3] = {(const float*)d_in[4], (const float*)d_in[10], (const float*)d_in[16]};
    const float* bhh[3] = {(const float*)d_in[5], (const float*)d_in[11], (const float*)d_in[17]};
    const float* Wl[3]  = {(const float*)d_in[6], (const float*)d_in[12], (const float*)d_in[18]};
    const float* bl[3]  = {(const float*)d_in[7], (const float*)d_in[13], (const float*)d_in[19]};
    const float* Wout = (const float*)d_in[20];
    const float* bout = (const float*)d_in[21];
    float* out = (float*)d_out;

    size_t lsm = (size_t)(TM * HP + 256 * GP) * 4 + (size_t)TM * DD * 4;   // 69,376 B

    cudaFuncSetAttribute(z_kernel, cudaFuncAttributeMaxDynamicSharedMemorySize, 72 * 1024);
    cudaFuncSetAttribute(lstm_ws_kernel, cudaFuncAttributeMaxDynamicSharedMemorySize, (int)lsm);
    cudaFuncSetAttribute(combine_kernel, cudaFuncAttributeMaxDynamicSharedMemorySize, 50 * 1024);

    dummy_kernel<<<1, 32>>>();   // keeps lstm layer-0 at ncu -s 5
    sort_kernel<<<(NN * 32 + 255) / 256, 256>>>(nbr);

    int hsel = 2;   // external (node_features)
    for (int l = 0; l < 3; l++) {
        int in_d = (l == 0) ? 3 : 64;
        size_t zsm = (size_t)(in_d * 256 + ZNB * in_d) * 4;
        z_kernel<<<(NN + ZNB - 1) / ZNB, 256, zsm>>>(nf, hsel, Wih[l], bih[l], bhh[l], in_d);

        lstm_ws_kernel<<<(NN + TM - 1) / TM, 256, lsm>>>(Whh[l]);

        int K = in_d + 64;
        size_t csm = (size_t)(K * 64 + CNB * K) * 4;
        int osel = (l & 1) ? 1 : 0;   // l0 -> hA, l1 -> hB, l2 -> hA
        combine_kernel<<<(NN + CNB - 1) / CNB, 256, csm>>>(nf, hsel, Wl[l], bl[l], osel, in_d);
        hsel = osel;
    }

    out_kernel<<<(NN * 32 + 255) / 256, 256>>>(hsel, Wout, bout, out);
}